// round 7
// baseline (speedup 1.0000x reference)
#include <cuda_runtime.h>

// Problem constants
#define BATCH  1024
#define FDIM   128
#define EDIM   256
#define HEADS  8
#define DHEAD  32
#define MROWS  (BATCH * FDIM)   // 131072

// Scratch for Q, K, V, R projections: 4 * 131072 * 256 floats = 512 MB.
// (__device__ global array: the sanctioned no-alloc scratch mechanism.)
__device__ float g_QKVR[(size_t)4 * MROWS * EDIM];

// ---------------------------------------------------------------------------
// Kernel 1: projections.  C[128x64 tile] = X[128x256] @ W[256x64-slice]
// Grid: (16, 1024).  blockIdx.x selects weight (bx>>2) and 64-col slice (bx&3).
// blockIdx.y selects the 128-row M tile.  K chunked by 32 with reg->smem
// double buffering.  Thread tile 8x4 (256 threads as 16x16).
// ---------------------------------------------------------------------------
constexpr int K1_SAP = 36;   // sA pitch (floats): 32 data + 4 pad
constexpr int K1_SBP = 68;   // sB pitch (floats): 64 data + 4 pad
constexpr int K1_SMEM = (2 * 128 * K1_SAP + 2 * 32 * K1_SBP) * 4;  // 54272 B

__global__ void __launch_bounds__(256, 2)
proj_kernel(const float* __restrict__ X,
            const float* __restrict__ Wq, const float* __restrict__ Wk,
            const float* __restrict__ Wv, const float* __restrict__ Wr)
{
    extern __shared__ float sm1[];
    float* sA = sm1;                       // [2][128][K1_SAP]
    float* sB = sm1 + 2 * 128 * K1_SAP;    // [2][32][K1_SBP]

    const int t    = threadIdx.x;
    const int bx   = blockIdx.x;
    const int m0   = blockIdx.y * 128;
    const int widx = bx >> 2;
    const int jo   = (bx & 3) * 64;
    const float* W = (widx == 0) ? Wq : (widx == 1) ? Wk : (widx == 2) ? Wv : Wr;
    float* out = g_QKVR + (size_t)widx * MROWS * EDIM;

    const int ti = t >> 4;   // 0..15 -> rows 8*ti..8*ti+7
    const int tj = t & 15;   // 0..15 -> cols 4*tj..4*tj+3

    // Staging coordinates (per-thread base; +256 per u step)
    const int ar = t >> 3, ac = t & 7;    // A: 1024 float4 = 128 rows x 8
    const int br = t >> 4, bc = t & 15;   // B: 512 float4  = 32 rows x 16
    const float* gA = X + (size_t)(m0 + ar) * EDIM + ac * 4;
    const float* gB = W + (size_t)br * EDIM + jo + bc * 4;

    float acc[8][4];
#pragma unroll
    for (int r = 0; r < 8; r++)
#pragma unroll
        for (int c = 0; c < 4; c++) acc[r][c] = 0.f;

    float4 ra[4], rb[2];

    // Prologue: load + store chunk 0
#pragma unroll
    for (int u = 0; u < 4; u++)
        ra[u] = *(const float4*)(gA + (size_t)u * 32 * EDIM);
#pragma unroll
    for (int u = 0; u < 2; u++)
        rb[u] = *(const float4*)(gB + (size_t)u * 16 * EDIM);
#pragma unroll
    for (int u = 0; u < 4; u++)
        *(float4*)(sA + (ar + 32 * u) * K1_SAP + ac * 4) = ra[u];
#pragma unroll
    for (int u = 0; u < 2; u++)
        *(float4*)(sB + (br + 16 * u) * K1_SBP + bc * 4) = rb[u];
    __syncthreads();

#pragma unroll 1
    for (int kc = 0; kc < 8; kc++) {
        const int p = kc & 1;
        if (kc < 7) {
            // Prefetch next chunk into registers (overlaps with compute)
#pragma unroll
            for (int u = 0; u < 4; u++)
                ra[u] = *(const float4*)(gA + (kc + 1) * 32 + (size_t)u * 32 * EDIM);
#pragma unroll
            for (int u = 0; u < 2; u++)
                rb[u] = *(const float4*)(gB + (size_t)((kc + 1) * 32) * EDIM
                                             + (size_t)u * 16 * EDIM);
        }
        const float* Ap = sA + p * 128 * K1_SAP + ti * 8 * K1_SAP;
        const float* Bp = sB + p * 32 * K1_SBP + tj * 4;
#pragma unroll 8
        for (int kk = 0; kk < 32; kk++) {
            float a[8];
#pragma unroll
            for (int r = 0; r < 8; r++) a[r] = Ap[r * K1_SAP + kk];
            const float4 bv = *(const float4*)(Bp + kk * K1_SBP);
#pragma unroll
            for (int r = 0; r < 8; r++) {
                acc[r][0] += a[r] * bv.x;
                acc[r][1] += a[r] * bv.y;
                acc[r][2] += a[r] * bv.z;
                acc[r][3] += a[r] * bv.w;
            }
        }
        if (kc < 7) {
            const int q = p ^ 1;  // buffer q last read at kc-1; safe to overwrite
#pragma unroll
            for (int u = 0; u < 4; u++)
                *(float4*)(sA + q * 128 * K1_SAP + (ar + 32 * u) * K1_SAP + ac * 4) = ra[u];
#pragma unroll
            for (int u = 0; u < 2; u++)
                *(float4*)(sB + q * 32 * K1_SBP + (br + 16 * u) * K1_SBP + bc * 4) = rb[u];
            __syncthreads();
        }
    }

    // Epilogue
    const int orow = m0 + ti * 8;
#pragma unroll
    for (int r = 0; r < 8; r++) {
        float4 v = make_float4(acc[r][0], acc[r][1], acc[r][2], acc[r][3]);
        *(float4*)(out + (size_t)(orow + r) * EDIM + jo + tj * 4) = v;
    }
}

// ---------------------------------------------------------------------------
// Kernel 2: per-(batch, head) attention.
// Grid: (8, 1024) = (head, batch).  256 threads.
//   sQ  [128][36]  : Q slice, row-major
//   sKT [32][132]  : K slice TRANSPOSED (k major) -> row-contiguous B reads
//   sV  [128][36]  : V slice
//   sS  [128][132] : scores, then unnormalized softmax probabilities
//   sInv[128]      : 1/rowsum (normalization folded into epilogue)
// ---------------------------------------------------------------------------
constexpr int K2_SQP = 36;
constexpr int K2_SKP = 132;
constexpr int K2_SVP = 36;
constexpr int K2_SSP = 132;
constexpr int K2_SMEM =
    (128 * K2_SQP + 32 * K2_SKP + 128 * K2_SVP + 128 * K2_SSP + 128) * 4;  // 121856 B

__global__ void __launch_bounds__(256, 1)
attn_kernel(float* __restrict__ out)
{
    extern __shared__ float sm2[];
    float* sQ   = sm2;
    float* sKT  = sQ + 128 * K2_SQP;
    float* sV   = sKT + 32 * K2_SKP;
    float* sS   = sV + 128 * K2_SVP;
    float* sInv = sS + 128 * K2_SSP;

    const int t = threadIdx.x;
    const int h = blockIdx.x;
    const int b = blockIdx.y;
    const size_t MN = (size_t)MROWS * EDIM;
    const float* Qg = g_QKVR + (size_t)b * FDIM * EDIM + h * DHEAD;
    const float* Kg = Qg + MN;
    const float* Vg = Qg + 2 * MN;
    const float* Rg = Qg + 3 * MN;

    // ---- Stage Q, V (row-major) and K (transposed) ----
    {
        const int r0 = t >> 3, c4 = t & 7;
#pragma unroll
        for (int u = 0; u < 4; u++) {
            const int r = r0 + 32 * u;
            const float4 q = *(const float4*)(Qg + (size_t)r * EDIM + c4 * 4);
            const float4 k = *(const float4*)(Kg + (size_t)r * EDIM + c4 * 4);
            const float4 v = *(const float4*)(Vg + (size_t)r * EDIM + c4 * 4);
            *(float4*)(sQ + r * K2_SQP + c4 * 4) = q;
            *(float4*)(sV + r * K2_SVP + c4 * 4) = v;
            sKT[(c4 * 4 + 0) * K2_SKP + r] = k.x;
            sKT[(c4 * 4 + 1) * K2_SKP + r] = k.y;
            sKT[(c4 * 4 + 2) * K2_SKP + r] = k.z;
            sKT[(c4 * 4 + 3) * K2_SKP + r] = k.w;
        }
    }
    __syncthreads();

    // ---- S = Q @ K^T  (128x128, K=32), thread tile 8x8 on a 16x16 grid ----
    {
        const int ti = t >> 4, tj = t & 15;
        float acc[8][8];
#pragma unroll
        for (int r = 0; r < 8; r++)
#pragma unroll
            for (int c = 0; c < 8; c++) acc[r][c] = 0.f;

        const float* Ap = sQ + ti * 8 * K2_SQP;
        const float* Bp = sKT + tj * 8;
#pragma unroll 4
        for (int k = 0; k < 32; k++) {
            float a[8];
#pragma unroll
            for (int r = 0; r < 8; r++) a[r] = Ap[r * K2_SQP + k];
            const float4 b0 = *(const float4*)(Bp + k * K2_SKP);
            const float4 b1 = *(const float4*)(Bp + k * K2_SKP + 4);
#pragma unroll
            for (int r = 0; r < 8; r++) {
                acc[r][0] += a[r] * b0.x; acc[r][1] += a[r] * b0.y;
                acc[r][2] += a[r] * b0.z; acc[r][3] += a[r] * b0.w;
                acc[r][4] += a[r] * b1.x; acc[r][5] += a[r] * b1.y;
                acc[r][6] += a[r] * b1.z; acc[r][7] += a[r] * b1.w;
            }
        }
        float* Sp = sS + ti * 8 * K2_SSP + tj * 8;
#pragma unroll
        for (int r = 0; r < 8; r++) {
            *(float4*)(Sp + r * K2_SSP)     = make_float4(acc[r][0], acc[r][1], acc[r][2], acc[r][3]);
            *(float4*)(Sp + r * K2_SSP + 4) = make_float4(acc[r][4], acc[r][5], acc[r][6], acc[r][7]);
        }
    }
    __syncthreads();

    // ---- Row softmax: store unnormalized exp; 1/sum in sInv ----
    if (t < 128) {
        float* row = sS + t * K2_SSP;
        float mx = -3.402823e38f;
#pragma unroll 8
        for (int j = 0; j < 32; j++) {
            const float4 v = *(const float4*)(row + j * 4);
            mx = fmaxf(mx, fmaxf(fmaxf(v.x, v.y), fmaxf(v.z, v.w)));
        }
        float sum = 0.f;
#pragma unroll 8
        for (int j = 0; j < 32; j++) {
            float4 v = *(const float4*)(row + j * 4);
            v.x = __expf(v.x - mx); v.y = __expf(v.y - mx);
            v.z = __expf(v.z - mx); v.w = __expf(v.w - mx);
            sum += (v.x + v.y) + (v.z + v.w);
            *(float4*)(row + j * 4) = v;
        }
        sInv[t] = 1.0f / sum;
    }
    __syncthreads();

    // ---- O = P @ V (128x32, K=128); epilogue: *inv + R, relu, store ----
    {
        const int ti = t >> 3, tj = t & 7;   // rows 4*ti.., cols 4*tj..
        float acc[4][4];
#pragma unroll
        for (int r = 0; r < 4; r++)
#pragma unroll
            for (int c = 0; c < 4; c++) acc[r][c] = 0.f;

        // Prefetch residual slice (hides LDG latency behind the GEMM)
        float4 rv[4];
#pragma unroll
        for (int r = 0; r < 4; r++)
            rv[r] = *(const float4*)(Rg + (size_t)(ti * 4 + r) * EDIM + tj * 4);

        const float* Ap = sS + ti * 4 * K2_SSP;
        const float* Bp = sV + tj * 4;
#pragma unroll 8
        for (int k = 0; k < 128; k++) {
            const float4 bv = *(const float4*)(Bp + k * K2_SVP);
            float a[4];
#pragma unroll
            for (int r = 0; r < 4; r++) a[r] = Ap[r * K2_SSP + k];
#pragma unroll
            for (int r = 0; r < 4; r++) {
                acc[r][0] += a[r] * bv.x; acc[r][1] += a[r] * bv.y;
                acc[r][2] += a[r] * bv.z; acc[r][3] += a[r] * bv.w;
            }
        }

        float* ob = out + (size_t)b * FDIM * EDIM + h * DHEAD;
#pragma unroll
        for (int r = 0; r < 4; r++) {
            const int row = ti * 4 + r;
            const float inv = sInv[row];
            float4 o;
            o.x = fmaxf(fmaf(acc[r][0], inv, rv[r].x), 0.f);
            o.y = fmaxf(fmaf(acc[r][1], inv, rv[r].y), 0.f);
            o.z = fmaxf(fmaf(acc[r][2], inv, rv[r].z), 0.f);
            o.w = fmaxf(fmaf(acc[r][3], inv, rv[r].w), 0.f);
            *(float4*)(ob + (size_t)row * EDIM + tj * 4) = o;
        }
    }
}

// ---------------------------------------------------------------------------
// Launch: inputs per metadata order:
//   d_in[0]=inputs [1024,128,256], d_in[1]=W_Query, d_in[2]=W_key,
//   d_in[3]=W_Value, d_in[4]=W_Res (all [256,256] fp32). Output fp32.
// ---------------------------------------------------------------------------
extern "C" void kernel_launch(void* const* d_in, const int* in_sizes, int n_in,
                              void* d_out, int out_size)
{
    const float* X  = (const float*)d_in[0];
    const float* Wq = (const float*)d_in[1];
    const float* Wk = (const float*)d_in[2];
    const float* Wv = (const float*)d_in[3];
    const float* Wr = (const float*)d_in[4];
    float* out = (float*)d_out;

    // Idempotent; host-side attribute set is legal during graph capture.
    cudaFuncSetAttribute(proj_kernel, cudaFuncAttributeMaxDynamicSharedMemorySize, K1_SMEM);
    cudaFuncSetAttribute(attn_kernel, cudaFuncAttributeMaxDynamicSharedMemorySize, K2_SMEM);

    proj_kernel<<<dim3(16, 1024), 256, K1_SMEM>>>(X, Wq, Wk, Wv, Wr);
    attn_kernel<<<dim3(8, 1024), 256, K2_SMEM>>>(out);
}